// round 2
// baseline (speedup 1.0000x reference)
#include <cuda_runtime.h>

#define N_PTS 8192
#define F_IN  784
#define H_DIM 128

// ---------------- scratch (static device globals; no runtime alloc) ----------
__device__ float  g_o1[N_PTS * H_DIM];          // selu(fc1) output, 4 MB
__device__ __align__(16) float2 g_o[N_PTS];     // final embedding [n,2]
__device__ float  g_bn_s [64 * H_DIM];
__device__ float  g_bn_s2[64 * H_DIM];
__device__ float  g_w2a[H_DIM];                 // fc2 row 0 * bn scale
__device__ float  g_w2b[H_DIM];                 // fc2 row 1 * bn scale
__device__ float  g_b2[2];                      // folded bias
__device__ float  g_part[256];                  // denom partials
__device__ float  g_inv_denom;

// ---------------- helpers ----------------------------------------------------
__device__ __forceinline__ float selu_f(float x) {
    const float alpha = 1.6732632423543772f;
    const float scale = 1.0507009873554805f;
    return x > 0.0f ? scale * x : scale * alpha * expm1f(x);
}

// FFMA-pipe reciprocal: bit-hack seed (<=~3.5% err) + 2 Newton steps -> ~1e-6 rel.
// Avoids MUFU.RCP which would cap the 64M-entry qij pass at ~450us.
__device__ __forceinline__ float fast_rcp(float x) {
    float y = __int_as_float(0x7EF311C3 - __float_as_int(x));
    y = y * fmaf(-x, y, 2.0f);
    y = y * fmaf(-x, y, 2.0f);
    return y;
}

// ---------------- K1: o1 = selu(x @ fc_w.T + fc_b) ---------------------------
// 64x128 block tile, 8x4 thread tile, KB=32. grid=128, block=256.
#define TM 64
#define TN 128
#define KB 32

__global__ __launch_bounds__(256) void k_gemm1(const float* __restrict__ x,
                                               const float* __restrict__ w,
                                               const float* __restrict__ b) {
    __shared__ float As[KB][TM + 4];   // padded rows
    __shared__ float Bs[KB][TN + 4];
    const int tid  = threadIdx.x;
    const int row0 = blockIdx.x * TM;
    const int r0 = (tid >> 5) * 8;     // 8 row-groups of 8
    const int c0 = (tid & 31) * 4;     // 32 col-groups of 4
    float acc[8][4] = {};

    for (int k0 = 0; k0 < F_IN; k0 += KB) {
        #pragma unroll
        for (int s = 0; s < 2; s++) {                 // A: 64x32 = 512 float4
            int id = tid + s * 256;
            int m = id >> 3, kg = (id & 7) * 4;
            int k = k0 + kg;
            float4 v = make_float4(0.f, 0.f, 0.f, 0.f);
            if (k < F_IN) v = *(const float4*)&x[(row0 + m) * F_IN + k];
            As[kg + 0][m] = v.x; As[kg + 1][m] = v.y;
            As[kg + 2][m] = v.z; As[kg + 3][m] = v.w;
        }
        #pragma unroll
        for (int s = 0; s < 4; s++) {                 // B: 128x32 = 1024 float4
            int id = tid + s * 256;
            int h = id >> 3, kg = (id & 7) * 4;
            int k = k0 + kg;
            float4 v = make_float4(0.f, 0.f, 0.f, 0.f);
            if (k < F_IN) v = *(const float4*)&w[h * F_IN + k];
            Bs[kg + 0][h] = v.x; Bs[kg + 1][h] = v.y;
            Bs[kg + 2][h] = v.z; Bs[kg + 3][h] = v.w;
        }
        __syncthreads();
        #pragma unroll
        for (int k = 0; k < KB; k++) {
            float a[8], bb[4];
            *(float4*)&a[0] = *(const float4*)&As[k][r0];
            *(float4*)&a[4] = *(const float4*)&As[k][r0 + 4];
            *(float4*)&bb[0] = *(const float4*)&Bs[k][c0];
            #pragma unroll
            for (int i = 0; i < 8; i++)
                #pragma unroll
                for (int j = 0; j < 4; j++)
                    acc[i][j] = fmaf(a[i], bb[j], acc[i][j]);
        }
        __syncthreads();
    }
    float4 bias = *(const float4*)&b[c0];
    #pragma unroll
    for (int i = 0; i < 8; i++) {
        float4 o;
        o.x = selu_f(acc[i][0] + bias.x);
        o.y = selu_f(acc[i][1] + bias.y);
        o.z = selu_f(acc[i][2] + bias.z);
        o.w = selu_f(acc[i][3] + bias.w);
        *(float4*)&g_o1[(row0 + r0 + i) * H_DIM + c0] = o;
    }
}

// ---------------- K2: BN partial column sums (deterministic, coalesced) ------
__global__ void k_bn_part(void) {
    int h = threadIdx.x;          // 128
    int blk = blockIdx.x;         // 64
    int row0 = blk * 128;
    float s = 0.f, s2 = 0.f;
    for (int r = 0; r < 128; r++) {
        float v = g_o1[(row0 + r) * H_DIM + h];
        s += v;
        s2 = fmaf(v, v, s2);
    }
    g_bn_s [blk * H_DIM + h] = s;
    g_bn_s2[blk * H_DIM + h] = s2;
}

// ---------------- K3: finalize BN, fold into fc2 weights ---------------------
__global__ void k_bn_finalize(const float* __restrict__ gamma,
                              const float* __restrict__ beta,
                              const float* __restrict__ w2,
                              const float* __restrict__ b2) {
    int h = threadIdx.x;          // 128
    float s = 0.f, s2 = 0.f;
    for (int blk = 0; blk < 64; blk++) {
        s  += g_bn_s [blk * H_DIM + h];
        s2 += g_bn_s2[blk * H_DIM + h];
    }
    float mu  = s  * (1.0f / N_PTS);
    float var = s2 * (1.0f / N_PTS) - mu * mu;
    float a  = gamma[h] * rsqrtf(var + 1e-5f);
    float bb = beta[h] - mu * a;
    float w0 = w2[h], w1 = w2[H_DIM + h];
    g_w2a[h] = w0 * a;
    g_w2b[h] = w1 * a;
    __shared__ float red0[128], red1[128];
    red0[h] = bb * w0;
    red1[h] = bb * w1;
    __syncthreads();
    for (int off = 64; off > 0; off >>= 1) {
        if (h < off) { red0[h] += red0[h + off]; red1[h] += red1[h + off]; }
        __syncthreads();
    }
    if (h == 0) {
        g_b2[0] = b2[0] + red0[0];
        g_b2[1] = b2[1] + red1[0];
    }
}

// ---------------- K4: o = selu(o1_bn @ fc2'.T + b2') -------------------------
__global__ __launch_bounds__(256) void k_fc2(float* __restrict__ out_o) {
    int w = threadIdx.x >> 5, lane = threadIdx.x & 31;
    int row = blockIdx.x * 8 + w;
    const float* rowp = &g_o1[row * H_DIM];
    float p0 = 0.f, p1 = 0.f;
    #pragma unroll
    for (int q = 0; q < 4; q++) {
        float v = rowp[lane + 32 * q];
        p0 = fmaf(v, g_w2a[lane + 32 * q], p0);
        p1 = fmaf(v, g_w2b[lane + 32 * q], p1);
    }
    #pragma unroll
    for (int off = 16; off > 0; off >>= 1) {
        p0 += __shfl_xor_sync(0xffffffffu, p0, off);
        p1 += __shfl_xor_sync(0xffffffffu, p1, off);
    }
    if (lane == 0) {
        float2 o;
        o.x = selu_f(p0 + g_b2[0]);
        o.y = selu_f(p1 + g_b2[1]);
        g_o[row] = o;
        *(float2*)&out_o[row * 2] = o;
    }
}

// ---------------- K5: denom = 2 * sum_{i<j} 1/(1+dis) ------------------------
// grid (8 jchunks, 32 itiles), block 256 (thread = one i row).
// Whole lower-triangle blocks exit immediately; diagonal blocks predicate.
__global__ __launch_bounds__(256) void k_denom(void) {
    __shared__ float2 oj[1024];
    __shared__ float red[256];
    int tid   = threadIdx.x;
    int jbase = blockIdx.x * 1024;
    int imin  = blockIdx.y * 256;
    int bid   = blockIdx.y * 8 + blockIdx.x;
    if (jbase + 1023 <= imin) {               // fully below diagonal: nothing
        if (tid == 0) g_part[bid] = 0.0f;
        return;
    }
    #pragma unroll
    for (int s = 0; s < 4; s++) oj[tid + s * 256] = g_o[jbase + tid + s * 256];
    __syncthreads();

    int i = imin + tid;
    float2 oi = g_o[i];
    float acc = 0.0f;
    if (jbase >= imin + 256) {                // fully above diagonal: no mask
        #pragma unroll 8
        for (int j = 0; j < 1024; j++) {
            float2 p = oj[j];
            float dx = oi.x - p.x, dy = oi.y - p.y;
            acc += fast_rcp(fmaf(dx, dx, fmaf(dy, dy, 1.0f)));
        }
    } else {                                  // diagonal block: mask j > i
        #pragma unroll 8
        for (int j = 0; j < 1024; j++) {
            float2 p = oj[j];
            float dx = oi.x - p.x, dy = oi.y - p.y;
            float r = fast_rcp(fmaf(dx, dx, fmaf(dy, dy, 1.0f)));
            acc += (jbase + j > i) ? r : 0.0f;
        }
    }
    red[tid] = acc;
    __syncthreads();
    for (int off = 128; off > 0; off >>= 1) {
        if (tid < off) red[tid] += red[tid + off];
        __syncthreads();
    }
    if (tid == 0) g_part[bid] = red[0];
}

__global__ void k_denom_final(void) {
    __shared__ float red[256];
    int tid = threadIdx.x;
    red[tid] = g_part[tid];
    __syncthreads();
    for (int off = 128; off > 0; off >>= 1) {
        if (tid < off) red[tid] += red[tid + off];
        __syncthreads();
    }
    if (tid == 0) g_inv_denom = 1.0f / (2.0f * red[0]);
}

// ---------------- K6: write qij = (1/(1+dis)) * inv_denom --------------------
// grid (8 jchunks, 1024 itiles of 8 rows), block 256 = 8 warps (warp = row).
// Each lane writes a float4 (coalesced 128B per warp-iter).
__global__ __launch_bounds__(256) void k_qij(float* __restrict__ out) {
    int w = threadIdx.x >> 5, lane = threadIdx.x & 31;
    int i = blockIdx.y * 8 + w;
    int jbase = blockIdx.x * 1024;
    float2 oi = g_o[i];
    float inv = g_inv_denom;
    const float4* op4 = (const float4*)g_o;
    float* outrow = out + (size_t)i * N_PTS;
    #pragma unroll
    for (int iter = 0; iter < 8; iter++) {
        int j = jbase + iter * 128 + lane * 4;
        float4 q0 = op4[(j >> 1)];        // o[j], o[j+1]
        float4 q1 = op4[(j >> 1) + 1];    // o[j+2], o[j+3]
        float4 r;
        { float dx = oi.x - q0.x, dy = oi.y - q0.y;
          r.x = fast_rcp(fmaf(dx, dx, fmaf(dy, dy, 1.0f))) * inv; }
        { float dx = oi.x - q0.z, dy = oi.y - q0.w;
          r.y = fast_rcp(fmaf(dx, dx, fmaf(dy, dy, 1.0f))) * inv; }
        { float dx = oi.x - q1.x, dy = oi.y - q1.y;
          r.z = fast_rcp(fmaf(dx, dx, fmaf(dy, dy, 1.0f))) * inv; }
        { float dx = oi.x - q1.z, dy = oi.y - q1.w;
          r.w = fast_rcp(fmaf(dx, dx, fmaf(dy, dy, 1.0f))) * inv; }
        *(float4*)&outrow[j] = r;
    }
}

// ---------------- launcher ---------------------------------------------------
extern "C" void kernel_launch(void* const* d_in, const int* in_sizes, int n_in,
                              void* d_out, int out_size) {
    (void)in_sizes; (void)n_in; (void)out_size;
    const float* x        = (const float*)d_in[0];
    const float* fc_w     = (const float*)d_in[1];
    const float* fc_b     = (const float*)d_in[2];
    const float* bn_gamma = (const float*)d_in[3];
    const float* bn_beta  = (const float*)d_in[4];
    const float* fc2_w    = (const float*)d_in[5];
    const float* fc2_b    = (const float*)d_in[6];
    float* out = (float*)d_out;
    float* out_qij = out;                               // [n, n]
    float* out_o   = out + (size_t)N_PTS * N_PTS;       // [n, 2]

    k_gemm1<<<N_PTS / TM, 256>>>(x, fc_w, fc_b);
    k_bn_part<<<64, 128>>>();
    k_bn_finalize<<<1, 128>>>(bn_gamma, bn_beta, fc2_w, fc2_b);
    k_fc2<<<N_PTS / 8, 256>>>(out_o);
    k_denom<<<dim3(8, 32), 256>>>();
    k_denom_final<<<1, 256>>>();
    k_qij<<<dim3(8, 1024), 256>>>(out_qij);
}

// round 7
// speedup vs baseline: 1.0599x; 1.0599x over previous
#include <cuda_runtime.h>
#include <cuda_bf16.h>

typedef unsigned int u32;

#define N_PTS 8192
#define F_IN  784
#define H_DIM 128

// ---------------- scratch (static device globals; no runtime alloc) ----------
__device__ float  g_o1[N_PTS * H_DIM];          // selu(fc1) output, 4 MB
__device__ __align__(16) float2 g_o[N_PTS];     // final embedding [n,2]
__device__ float  g_bn_s [64 * H_DIM];
__device__ float  g_bn_s2[64 * H_DIM];
__device__ float  g_w2a[H_DIM];                 // fc2 row 0 * bn scale
__device__ float  g_w2b[H_DIM];                 // fc2 row 1 * bn scale
__device__ float  g_b2[2];                      // folded bias
__device__ float  g_part[256];                  // denom partials
__device__ float  g_inv_denom;

// ---------------- helpers ----------------------------------------------------
__device__ __forceinline__ float selu_f(float x) {
    const float alpha = 1.6732632423543772f;
    const float scale = 1.0507009873554805f;
    return x > 0.0f ? scale * x : scale * alpha * expm1f(x);
}

// FFMA-pipe reciprocal: bit-hack seed (<=~3.5% err) + 2 Newton steps -> ~1e-6 rel.
__device__ __forceinline__ float fast_rcp(float x) {
    float y = __int_as_float(0x7EF311C3 - __float_as_int(x));
    y = y * fmaf(-x, y, 2.0f);
    y = y * fmaf(-x, y, 2.0f);
    return y;
}

__device__ __forceinline__ u32 bfpack(__nv_bfloat16 a, __nv_bfloat16 b) {
    return (u32)__bfloat16_as_ushort(a) |
           ((u32)__bfloat16_as_ushort(b) << 16);
}

// split (x,y) into bf16 hi pair + bf16 residual pair
__device__ __forceinline__ void split2(float x, float y, u32& h, u32& l) {
    __nv_bfloat16 hx = __float2bfloat16_rn(x), hy = __float2bfloat16_rn(y);
    float rx = x - __bfloat162float(hx);
    float ry = y - __bfloat162float(hy);
    h = bfpack(hx, hy);
    l = bfpack(__float2bfloat16_rn(rx), __float2bfloat16_rn(ry));
}

__device__ __forceinline__ void mma_bf16(float c[4], const u32 a[4],
                                         u32 b0, u32 b1) {
    asm volatile(
        "mma.sync.aligned.m16n8k16.row.col.f32.bf16.bf16.f32 "
        "{%0,%1,%2,%3}, {%4,%5,%6,%7}, {%8,%9}, {%0,%1,%2,%3};\n"
        : "+f"(c[0]), "+f"(c[1]), "+f"(c[2]), "+f"(c[3])
        : "r"(a[0]), "r"(a[1]), "r"(a[2]), "r"(a[3]), "r"(b0), "r"(b1));
}

// ---------------- K1: o1 = selu(x @ fc_w.T + fc_b) via bf16x3 tensor cores ---
// Block tile 64x128, 8 warps (2m x 4n), warp tile 32x32, BK=16 (49 iters).
// SMEM rows padded to 24 bf16 (12 words): fragment loads are bank-conflict-free.
__global__ __launch_bounds__(256) void k_gemm1(const float* __restrict__ x,
                                               const float* __restrict__ w,
                                               const float* __restrict__ b) {
    __shared__ u32 As_hi[64 * 12], As_lo[64 * 12];
    __shared__ u32 Bs_hi[128 * 12], Bs_lo[128 * 12];

    const int tid  = threadIdx.x;
    const int row0 = blockIdx.x * 64;
    const int lane = tid & 31;
    const int warp = tid >> 5;
    const int wm = warp >> 2;          // 0..1
    const int wn = warp & 3;           // 0..3
    const int gr = lane >> 2, gc = lane & 3;

    float acc[2][4][4] = {};

    // per-iter gmem load coords
    const int a_row = tid >> 2, a_c = tid & 3;          // A: 64 rows x 4 float4
    const int b_n = tid >> 1, b_c = tid & 1;            // B: 128 rows x 2 float4-pairs

    for (int k0 = 0; k0 < F_IN; k0 += 16) {
        // ---- stage A tile (64x16) ----
        {
            float4 v = *(const float4*)&x[(size_t)(row0 + a_row) * F_IN + k0 + a_c * 4];
            u32 h0, l0, h1, l1;
            split2(v.x, v.y, h0, l0);
            split2(v.z, v.w, h1, l1);
            *(uint2*)&As_hi[a_row * 12 + a_c * 2] = make_uint2(h0, h1);
            *(uint2*)&As_lo[a_row * 12 + a_c * 2] = make_uint2(l0, l1);
        }
        // ---- stage B tile (128x16) ----
        {
            const float* wp = &w[(size_t)b_n * F_IN + k0 + b_c * 8];
            float4 v0 = *(const float4*)wp;
            float4 v1 = *(const float4*)(wp + 4);
            u32 h0, l0, h1, l1, h2, l2, h3, l3;
            split2(v0.x, v0.y, h0, l0); split2(v0.z, v0.w, h1, l1);
            split2(v1.x, v1.y, h2, l2); split2(v1.z, v1.w, h3, l3);
            *(uint4*)&Bs_hi[b_n * 12 + b_c * 4] = make_uint4(h0, h1, h2, h3);
            *(uint4*)&Bs_lo[b_n * 12 + b_c * 4] = make_uint4(l0, l1, l2, l3);
        }
        __syncthreads();

        // ---- fragments + mma ----
        u32 ah[2][4], al[2][4];
        #pragma unroll
        for (int mt = 0; mt < 2; mt++) {
            int r = wm * 32 + mt * 16 + gr;
            ah[mt][0] = As_hi[r * 12 + gc];
            ah[mt][1] = As_hi[(r + 8) * 12 + gc];
            ah[mt][2] = As_hi[r * 12 + gc + 4];
            ah[mt][3] = As_hi[(r + 8) * 12 + gc + 4];
            al[mt][0] = As_lo[r * 12 + gc];
            al[mt][1] = As_lo[(r + 8) * 12 + gc];
            al[mt][2] = As_lo[r * 12 + gc + 4];
            al[mt][3] = As_lo[(r + 8) * 12 + gc + 4];
        }
        #pragma unroll
        for (int nt = 0; nt < 4; nt++) {
            int n = wn * 32 + nt * 8 + gr;
            u32 bh0 = Bs_hi[n * 12 + gc], bh1 = Bs_hi[n * 12 + gc + 4];
            u32 bl0 = Bs_lo[n * 12 + gc], bl1 = Bs_lo[n * 12 + gc + 4];
            #pragma unroll
            for (int mt = 0; mt < 2; mt++) {
                mma_bf16(acc[mt][nt], ah[mt], bh0, bh1);   // hi*hi
                mma_bf16(acc[mt][nt], ah[mt], bl0, bl1);   // hi*lo
                mma_bf16(acc[mt][nt], al[mt], bh0, bh1);   // lo*hi
            }
        }
        __syncthreads();
    }

    // ---- epilogue: bias + selu + store ----
    #pragma unroll
    for (int mt = 0; mt < 2; mt++) {
        int r = row0 + wm * 32 + mt * 16 + gr;
        #pragma unroll
        for (int nt = 0; nt < 4; nt++) {
            int n0 = wn * 32 + nt * 8 + 2 * gc;
            float2 bias = *(const float2*)&b[n0];
            float2 o0, o1;
            o0.x = selu_f(acc[mt][nt][0] + bias.x);
            o0.y = selu_f(acc[mt][nt][1] + bias.y);
            o1.x = selu_f(acc[mt][nt][2] + bias.x);
            o1.y = selu_f(acc[mt][nt][3] + bias.y);
            *(float2*)&g_o1[(size_t)r * H_DIM + n0]       = o0;
            *(float2*)&g_o1[(size_t)(r + 8) * H_DIM + n0] = o1;
        }
    }
}

// ---------------- K2: BN partial column sums ---------------------------------
__global__ void k_bn_part(void) {
    int h = threadIdx.x;          // 128
    int blk = blockIdx.x;         // 64
    int row0 = blk * 128;
    float s = 0.f, s2 = 0.f;
    for (int r = 0; r < 128; r++) {
        float v = g_o1[(row0 + r) * H_DIM + h];
        s += v;
        s2 = fmaf(v, v, s2);
    }
    g_bn_s [blk * H_DIM + h] = s;
    g_bn_s2[blk * H_DIM + h] = s2;
}

// ---------------- K3: finalize BN, fold into fc2 weights ---------------------
__global__ void k_bn_finalize(const float* __restrict__ gamma,
                              const float* __restrict__ beta,
                              const float* __restrict__ w2,
                              const float* __restrict__ b2) {
    int h = threadIdx.x;          // 128
    float s = 0.f, s2 = 0.f;
    for (int blk = 0; blk < 64; blk++) {
        s  += g_bn_s [blk * H_DIM + h];
        s2 += g_bn_s2[blk * H_DIM + h];
    }
    float mu  = s  * (1.0f / N_PTS);
    float var = s2 * (1.0f / N_PTS) - mu * mu;
    float a  = gamma[h] * rsqrtf(var + 1e-5f);
    float bb = beta[h] - mu * a;
    float w0 = w2[h], w1 = w2[H_DIM + h];
    g_w2a[h] = w0 * a;
    g_w2b[h] = w1 * a;
    __shared__ float red0[128], red1[128];
    red0[h] = bb * w0;
    red1[h] = bb * w1;
    __syncthreads();
    for (int off = 64; off > 0; off >>= 1) {
        if (h < off) { red0[h] += red0[h + off]; red1[h] += red1[h + off]; }
        __syncthreads();
    }
    if (h == 0) {
        g_b2[0] = b2[0] + red0[0];
        g_b2[1] = b2[1] + red1[0];
    }
}

// ---------------- K4: o = selu(o1_bn @ fc2'.T + b2') -------------------------
__global__ __launch_bounds__(256) void k_fc2(float* __restrict__ out_o) {
    int w = threadIdx.x >> 5, lane = threadIdx.x & 31;
    int row = blockIdx.x * 8 + w;
    const float* rowp = &g_o1[row * H_DIM];
    float p0 = 0.f, p1 = 0.f;
    #pragma unroll
    for (int q = 0; q < 4; q++) {
        float v = rowp[lane + 32 * q];
        p0 = fmaf(v, g_w2a[lane + 32 * q], p0);
        p1 = fmaf(v, g_w2b[lane + 32 * q], p1);
    }
    #pragma unroll
    for (int off = 16; off > 0; off >>= 1) {
        p0 += __shfl_xor_sync(0xffffffffu, p0, off);
        p1 += __shfl_xor_sync(0xffffffffu, p1, off);
    }
    if (lane == 0) {
        float2 o;
        o.x = selu_f(p0 + g_b2[0]);
        o.y = selu_f(p1 + g_b2[1]);
        g_o[row] = o;
        *(float2*)&out_o[row * 2] = o;
    }
}

// ---------------- K5: denom = 2 * sum_{i<j} 1/(1+dis) ------------------------
__global__ __launch_bounds__(256) void k_denom(void) {
    __shared__ float2 oj[1024];
    __shared__ float red[256];
    int tid   = threadIdx.x;
    int jbase = blockIdx.x * 1024;
    int imin  = blockIdx.y * 256;
    int bid   = blockIdx.y * 8 + blockIdx.x;
    if (jbase + 1023 <= imin) {               // fully below diagonal: nothing
        if (tid == 0) g_part[bid] = 0.0f;
        return;
    }
    #pragma unroll
    for (int s = 0; s < 4; s++) oj[tid + s * 256] = g_o[jbase + tid + s * 256];
    __syncthreads();

    int i = imin + tid;
    float2 oi = g_o[i];
    float acc = 0.0f;
    if (jbase >= imin + 256) {                // fully above diagonal: no mask
        #pragma unroll 8
        for (int j = 0; j < 1024; j++) {
            float2 p = oj[j];
            float dx = oi.x - p.x, dy = oi.y - p.y;
            acc += fast_rcp(fmaf(dx, dx, fmaf(dy, dy, 1.0f)));
        }
    } else {                                  // diagonal block: mask j > i
        #pragma unroll 8
        for (int j = 0; j < 1024; j++) {
            float2 p = oj[j];
            float dx = oi.x - p.x, dy = oi.y - p.y;
            float r = fast_rcp(fmaf(dx, dx, fmaf(dy, dy, 1.0f)));
            acc += (jbase + j > i) ? r : 0.0f;
        }
    }
    red[tid] = acc;
    __syncthreads();
    for (int off = 128; off > 0; off >>= 1) {
        if (tid < off) red[tid] += red[tid + off];
        __syncthreads();
    }
    if (tid == 0) g_part[bid] = red[0];
}

__global__ void k_denom_final(void) {
    __shared__ float red[256];
    int tid = threadIdx.x;
    red[tid] = g_part[tid];
    __syncthreads();
    for (int off = 128; off > 0; off >>= 1) {
        if (tid < off) red[tid] += red[tid + off];
        __syncthreads();
    }
    if (tid == 0) g_inv_denom = 1.0f / (2.0f * red[0]);
}

// ---------------- K6: write qij = (1/(1+dis)) * inv_denom --------------------
__global__ __launch_bounds__(256) void k_qij(float* __restrict__ out) {
    int w = threadIdx.x >> 5, lane = threadIdx.x & 31;
    int i = blockIdx.y * 8 + w;
    int jbase = blockIdx.x * 1024;
    float2 oi = g_o[i];
    float inv = g_inv_denom;
    const float4* op4 = (const float4*)g_o;
    float* outrow = out + (size_t)i * N_PTS;
    #pragma unroll
    for (int iter = 0; iter < 8; iter++) {
        int j = jbase + iter * 128 + lane * 4;
        float4 q0 = op4[(j >> 1)];        // o[j], o[j+1]
        float4 q1 = op4[(j >> 1) + 1];    // o[j+2], o[j+3]
        float4 r;
        { float dx = oi.x - q0.x, dy = oi.y - q0.y;
          r.x = fast_rcp(fmaf(dx, dx, fmaf(dy, dy, 1.0f))) * inv; }
        { float dx = oi.x - q0.z, dy = oi.y - q0.w;
          r.y = fast_rcp(fmaf(dx, dx, fmaf(dy, dy, 1.0f))) * inv; }
        { float dx = oi.x - q1.x, dy = oi.y - q1.y;
          r.z = fast_rcp(fmaf(dx, dx, fmaf(dy, dy, 1.0f))) * inv; }
        { float dx = oi.x - q1.z, dy = oi.y - q1.w;
          r.w = fast_rcp(fmaf(dx, dx, fmaf(dy, dy, 1.0f))) * inv; }
        *(float4*)&outrow[j] = r;
    }
}

// ---------------- launcher ---------------------------------------------------
extern "C" void kernel_launch(void* const* d_in, const int* in_sizes, int n_in,
                              void* d_out, int out_size) {
    (void)in_sizes; (void)n_in; (void)out_size;
    const float* x        = (const float*)d_in[0];
    const float* fc_w     = (const float*)d_in[1];
    const float* fc_b     = (const float*)d_in[2];
    const float* bn_gamma = (const float*)d_in[3];
    const float* bn_beta  = (const float*)d_in[4];
    const float* fc2_w    = (const float*)d_in[5];
    const float* fc2_b    = (const float*)d_in[6];
    float* out = (float*)d_out;
    float* out_qij = out;                               // [n, n]
    float* out_o   = out + (size_t)N_PTS * N_PTS;       // [n, 2]

    k_gemm1<<<N_PTS / 64, 256>>>(x, fc_w, fc_b);
    k_bn_part<<<64, 128>>>();
    k_bn_finalize<<<1, 128>>>(bn_gamma, bn_beta, fc2_w, fc2_b);
    k_fc2<<<N_PTS / 8, 256>>>(out_o);
    k_denom<<<dim3(8, 32), 256>>>();
    k_denom_final<<<1, 256>>>();
    k_qij<<<dim3(8, 1024), 256>>>(out_qij);
}

// round 10
// speedup vs baseline: 1.2113x; 1.1428x over previous
#include <cuda_runtime.h>
#include <cuda_bf16.h>

typedef unsigned int u32;

#define N_PTS 8192
#define F_IN  784
#define H_DIM 128

// ---------------- scratch (static device globals; no runtime alloc) ----------
__device__ __align__(16) float  g_o1[N_PTS * H_DIM];   // selu(fc1) output, 4 MB
__device__ __align__(16) float2 g_o[N_PTS];            // final embedding [n,2]
__device__ float  g_bn_s [128 * H_DIM];                // per-gemm-block partials
__device__ float  g_bn_s2[128 * H_DIM];
__device__ __align__(16) float g_w2a[H_DIM];           // fc2 row 0 * bn scale
__device__ __align__(16) float g_w2b[H_DIM];           // fc2 row 1 * bn scale
__device__ float  g_b2[2];                             // folded bias
__device__ float  g_part[256];                         // denom partials

// ---------------- helpers ----------------------------------------------------
__device__ __forceinline__ float selu_f(float x) {
    const float alpha = 1.6732632423543772f;
    const float scale = 1.0507009873554805f;
    return x > 0.0f ? scale * x : scale * alpha * expm1f(x);
}

// FFMA-pipe reciprocal: bit-hack seed + 2 Newton steps -> ~1e-6 rel.
__device__ __forceinline__ float fast_rcp(float x) {
    float y = __int_as_float(0x7EF311C3 - __float_as_int(x));
    y = y * fmaf(-x, y, 2.0f);
    y = y * fmaf(-x, y, 2.0f);
    return y;
}

__device__ __forceinline__ u32 bfpack(__nv_bfloat16 a, __nv_bfloat16 b) {
    return (u32)__bfloat16_as_ushort(a) |
           ((u32)__bfloat16_as_ushort(b) << 16);
}

__device__ __forceinline__ void split2(float x, float y, u32& h, u32& l) {
    __nv_bfloat16 hx = __float2bfloat16_rn(x), hy = __float2bfloat16_rn(y);
    float rx = x - __bfloat162float(hx);
    float ry = y - __bfloat162float(hy);
    h = bfpack(hx, hy);
    l = bfpack(__float2bfloat16_rn(rx), __float2bfloat16_rn(ry));
}

__device__ __forceinline__ void mma_bf16(float c[4], const u32 a[4],
                                         u32 b0, u32 b1) {
    asm volatile(
        "mma.sync.aligned.m16n8k16.row.col.f32.bf16.bf16.f32 "
        "{%0,%1,%2,%3}, {%4,%5,%6,%7}, {%8,%9}, {%0,%1,%2,%3};\n"
        : "+f"(c[0]), "+f"(c[1]), "+f"(c[2]), "+f"(c[3])
        : "r"(a[0]), "r"(a[1]), "r"(a[2]), "r"(a[3]), "r"(b0), "r"(b1));
}

// ---------------- K1: o1 = selu(x @ fc_w.T + fc_b), bf16x3 TC + BN partials --
// Block tile 64x128, 8 warps (2m x 4n), BK=16 (49 iters), register prefetch.
__global__ __launch_bounds__(256) void k_gemm1(const float* __restrict__ x,
                                               const float* __restrict__ w,
                                               const float* __restrict__ b) {
    __shared__ u32 As_hi[64 * 12], As_lo[64 * 12];
    __shared__ u32 Bs_hi[128 * 12], Bs_lo[128 * 12];

    const int tid  = threadIdx.x;
    const int row0 = blockIdx.x * 64;
    const int lane = tid & 31;
    const int warp = tid >> 5;
    const int wm = warp >> 2;
    const int wn = warp & 3;
    const int gr = lane >> 2, gc = lane & 3;

    float acc[2][4][4] = {};

    const int a_row = tid >> 2, a_c = tid & 3;   // A: 64 rows x 4 float4
    const int b_n = tid >> 1, b_c = tid & 1;     // B: 128 rows x 2 float4-pairs

    // prefetch first tile into registers
    float4 va  = *(const float4*)&x[(size_t)(row0 + a_row) * F_IN + a_c * 4];
    const float* wp0 = &w[(size_t)b_n * F_IN + b_c * 8];
    float4 vb0 = *(const float4*)wp0;
    float4 vb1 = *(const float4*)(wp0 + 4);

    for (int k0 = 0; k0 < F_IN; k0 += 16) {
        // ---- stage current tile from registers ----
        {
            u32 h0, l0, h1, l1;
            split2(va.x, va.y, h0, l0);
            split2(va.z, va.w, h1, l1);
            *(uint2*)&As_hi[a_row * 12 + a_c * 2] = make_uint2(h0, h1);
            *(uint2*)&As_lo[a_row * 12 + a_c * 2] = make_uint2(l0, l1);
        }
        {
            u32 h0, l0, h1, l1, h2, l2, h3, l3;
            split2(vb0.x, vb0.y, h0, l0); split2(vb0.z, vb0.w, h1, l1);
            split2(vb1.x, vb1.y, h2, l2); split2(vb1.z, vb1.w, h3, l3);
            *(uint4*)&Bs_hi[b_n * 12 + b_c * 4] = make_uint4(h0, h1, h2, h3);
            *(uint4*)&Bs_lo[b_n * 12 + b_c * 4] = make_uint4(l0, l1, l2, l3);
        }
        __syncthreads();

        // ---- prefetch next tile (overlaps MMA below) ----
        if (k0 + 16 < F_IN) {
            va  = *(const float4*)&x[(size_t)(row0 + a_row) * F_IN + (k0 + 16) + a_c * 4];
            const float* wp = &w[(size_t)b_n * F_IN + (k0 + 16) + b_c * 8];
            vb0 = *(const float4*)wp;
            vb1 = *(const float4*)(wp + 4);
        }

        // ---- fragments + mma ----
        u32 ah[2][4], al[2][4];
        #pragma unroll
        for (int mt = 0; mt < 2; mt++) {
            int r = wm * 32 + mt * 16 + gr;
            ah[mt][0] = As_hi[r * 12 + gc];
            ah[mt][1] = As_hi[(r + 8) * 12 + gc];
            ah[mt][2] = As_hi[r * 12 + gc + 4];
            ah[mt][3] = As_hi[(r + 8) * 12 + gc + 4];
            al[mt][0] = As_lo[r * 12 + gc];
            al[mt][1] = As_lo[(r + 8) * 12 + gc];
            al[mt][2] = As_lo[r * 12 + gc + 4];
            al[mt][3] = As_lo[(r + 8) * 12 + gc + 4];
        }
        #pragma unroll
        for (int nt = 0; nt < 4; nt++) {
            int n = wn * 32 + nt * 8 + gr;
            u32 bh0 = Bs_hi[n * 12 + gc], bh1 = Bs_hi[n * 12 + gc + 4];
            u32 bl0 = Bs_lo[n * 12 + gc], bl1 = Bs_lo[n * 12 + gc + 4];
            #pragma unroll
            for (int mt = 0; mt < 2; mt++) {
                mma_bf16(acc[mt][nt], ah[mt], bh0, bh1);   // hi*hi
                mma_bf16(acc[mt][nt], ah[mt], bl0, bl1);   // hi*lo
                mma_bf16(acc[mt][nt], al[mt], bh0, bh1);   // lo*hi
            }
        }
        __syncthreads();
    }

    // ---- epilogue: bias + selu + store ----
    #pragma unroll
    for (int mt = 0; mt < 2; mt++) {
        int r = row0 + wm * 32 + mt * 16 + gr;
        #pragma unroll
        for (int nt = 0; nt < 4; nt++) {
            int n0 = wn * 32 + nt * 8 + 2 * gc;
            float2 bias = *(const float2*)&b[n0];
            float2 o0, o1;
            o0.x = selu_f(acc[mt][nt][0] + bias.x);
            o0.y = selu_f(acc[mt][nt][1] + bias.y);
            o1.x = selu_f(acc[mt][nt][2] + bias.x);
            o1.y = selu_f(acc[mt][nt][3] + bias.y);
            *(float2*)&g_o1[(size_t)r * H_DIM + n0]       = o0;
            *(float2*)&g_o1[(size_t)(r + 8) * H_DIM + n0] = o1;
        }
    }

    // ---- fused BN partial sums over this block's 64 rows (L2-hot) ----
    __syncthreads();     // block-scope fence: epilogue stores visible below
    if (tid < H_DIM) {
        float s = 0.f, s2 = 0.f;
        for (int r = 0; r < 64; r++) {
            float v = g_o1[(size_t)(row0 + r) * H_DIM + tid];
            s += v;
            s2 = fmaf(v, v, s2);
        }
        g_bn_s [blockIdx.x * H_DIM + tid] = s;
        g_bn_s2[blockIdx.x * H_DIM + tid] = s2;
    }
}

// ---------------- K2: finalize BN, fold into fc2 weights ---------------------
__global__ void k_bn_finalize(const float* __restrict__ gamma,
                              const float* __restrict__ beta,
                              const float* __restrict__ w2,
                              const float* __restrict__ b2) {
    int h = threadIdx.x;          // 128
    float s = 0.f, s2 = 0.f;
    for (int blk = 0; blk < 128; blk++) {
        s  += g_bn_s [blk * H_DIM + h];
        s2 += g_bn_s2[blk * H_DIM + h];
    }
    float mu  = s  * (1.0f / N_PTS);
    float var = s2 * (1.0f / N_PTS) - mu * mu;
    float a  = gamma[h] * rsqrtf(var + 1e-5f);
    float bb = beta[h] - mu * a;
    float w0 = w2[h], w1 = w2[H_DIM + h];
    g_w2a[h] = w0 * a;
    g_w2b[h] = w1 * a;
    __shared__ float red0[128], red1[128];
    red0[h] = bb * w0;
    red1[h] = bb * w1;
    __syncthreads();
    for (int off = 64; off > 0; off >>= 1) {
        if (h < off) { red0[h] += red0[h + off]; red1[h] += red1[h + off]; }
        __syncthreads();
    }
    if (h == 0) {
        g_b2[0] = b2[0] + red0[0];
        g_b2[1] = b2[1] + red1[0];
    }
}

// ---------------- K3: o = selu(o1_bn @ fc2'.T + b2'), float4 loads -----------
__global__ __launch_bounds__(256) void k_fc2(float* __restrict__ out_o) {
    int w = threadIdx.x >> 5, lane = threadIdx.x & 31;
    float4 wa = *(const float4*)&g_w2a[lane * 4];
    float4 wb = *(const float4*)&g_w2b[lane * 4];
    #pragma unroll
    for (int rr = 0; rr < 2; rr++) {
        int row = blockIdx.x * 16 + w * 2 + rr;
        float4 v = *(const float4*)&g_o1[(size_t)row * H_DIM + lane * 4];
        float p0 = fmaf(v.x, wa.x, fmaf(v.y, wa.y, fmaf(v.z, wa.z, v.w * wa.w)));
        float p1 = fmaf(v.x, wb.x, fmaf(v.y, wb.y, fmaf(v.z, wb.z, v.w * wb.w)));
        #pragma unroll
        for (int off = 16; off > 0; off >>= 1) {
            p0 += __shfl_xor_sync(0xffffffffu, p0, off);
            p1 += __shfl_xor_sync(0xffffffffu, p1, off);
        }
        if (lane == 0) {
            float2 o;
            o.x = selu_f(p0 + g_b2[0]);
            o.y = selu_f(p1 + g_b2[1]);
            g_o[row] = o;
            *(float2*)&out_o[row * 2] = o;
        }
    }
}

// ---------------- K4: denom partials = sum_{i<j} 1/(1+dis) -------------------
__global__ __launch_bounds__(256) void k_denom(void) {
    __shared__ float2 oj[1024];
    __shared__ float red[256];
    int tid   = threadIdx.x;
    int jbase = blockIdx.x * 1024;
    int imin  = blockIdx.y * 256;
    int bid   = blockIdx.y * 8 + blockIdx.x;
    if (jbase + 1023 <= imin) {               // fully below diagonal
        if (tid == 0) g_part[bid] = 0.0f;
        return;
    }
    #pragma unroll
    for (int s = 0; s < 4; s++) oj[tid + s * 256] = g_o[jbase + tid + s * 256];
    __syncthreads();

    int i = imin + tid;
    float2 oi = g_o[i];
    float acc = 0.0f;
    if (jbase >= imin + 256) {                // fully above diagonal
        #pragma unroll 8
        for (int j = 0; j < 1024; j++) {
            float2 p = oj[j];
            float dx = oi.x - p.x, dy = oi.y - p.y;
            acc += fast_rcp(fmaf(dx, dx, fmaf(dy, dy, 1.0f)));
        }
    } else {                                  // diagonal block: mask j > i
        #pragma unroll 8
        for (int j = 0; j < 1024; j++) {
            float2 p = oj[j];
            float dx = oi.x - p.x, dy = oi.y - p.y;
            float r = fast_rcp(fmaf(dx, dx, fmaf(dy, dy, 1.0f)));
            acc += (jbase + j > i) ? r : 0.0f;
        }
    }
    red[tid] = acc;
    __syncthreads();
    for (int off = 128; off > 0; off >>= 1) {
        if (tid < off) red[tid] += red[tid + off];
        __syncthreads();
    }
    if (tid == 0) g_part[bid] = red[0];
}

// ---------------- K5: qij = (1/(1+dis)) * inv_denom (denom folded in) --------
__global__ __launch_bounds__(256) void k_qij(float* __restrict__ out) {
    __shared__ float red[256];
    int tid = threadIdx.x;
    red[tid] = g_part[tid];                   // identical fixed-order reduce in
    __syncthreads();                          // every block -> same inv everywhere
    #pragma unroll
    for (int off = 128; off > 0; off >>= 1) {
        if (tid < off) red[tid] += red[tid + off];
        __syncthreads();
    }
    float inv = 1.0f / (2.0f * red[0]);

    int w = tid >> 5, lane = tid & 31;
    int i = blockIdx.y * 8 + w;
    int jbase = blockIdx.x * 1024;
    float2 oi = g_o[i];
    const float4* op4 = (const float4*)g_o;
    float* outrow = out + (size_t)i * N_PTS;
    #pragma unroll
    for (int iter = 0; iter < 8; iter++) {
        int j = jbase + iter * 128 + lane * 4;
        float4 q0 = op4[(j >> 1)];
        float4 q1 = op4[(j >> 1) + 1];
        float4 r;
        { float dx = oi.x - q0.x, dy = oi.y - q0.y;
          r.x = fast_rcp(fmaf(dx, dx, fmaf(dy, dy, 1.0f))) * inv; }
        { float dx = oi.x - q0.z, dy = oi.y - q0.w;
          r.y = fast_rcp(fmaf(dx, dx, fmaf(dy, dy, 1.0f))) * inv; }
        { float dx = oi.x - q1.x, dy = oi.y - q1.y;
          r.z = fast_rcp(fmaf(dx, dx, fmaf(dy, dy, 1.0f))) * inv; }
        { float dx = oi.x - q1.z, dy = oi.y - q1.w;
          r.w = fast_rcp(fmaf(dx, dx, fmaf(dy, dy, 1.0f))) * inv; }
        *(float4*)&outrow[j] = r;
    }
}

// ---------------- launcher ---------------------------------------------------
extern "C" void kernel_launch(void* const* d_in, const int* in_sizes, int n_in,
                              void* d_out, int out_size) {
    (void)in_sizes; (void)n_in; (void)out_size;
    const float* x        = (const float*)d_in[0];
    const float* fc_w     = (const float*)d_in[1];
    const float* fc_b     = (const float*)d_in[2];
    const float* bn_gamma = (const float*)d_in[3];
    const float* bn_beta  = (const float*)d_in[4];
    const float* fc2_w    = (const float*)d_in[5];
    const float* fc2_b    = (const float*)d_in[6];
    float* out = (float*)d_out;
    float* out_qij = out;                               // [n, n]
    float* out_o   = out + (size_t)N_PTS * N_PTS;       // [n, 2]

    k_gemm1<<<N_PTS / 64, 256>>>(x, fc_w, fc_b);
    k_bn_finalize<<<1, 128>>>(bn_gamma, bn_beta, fc2_w, fc2_b);
    k_fc2<<<N_PTS / 16, 256>>>(out_o);
    k_denom<<<dim3(8, 32), 256>>>();
    k_qij<<<dim3(8, 1024), 256>>>(out_qij);
}

// round 11
// speedup vs baseline: 1.2833x; 1.0595x over previous
#include <cuda_runtime.h>
#include <cuda_bf16.h>

typedef unsigned int u32;

#define N_PTS 8192
#define F_IN  784
#define H_DIM 128

// ---------------- scratch (static device globals; no runtime alloc) ----------
__device__ __align__(16) float  g_o1[N_PTS * H_DIM];   // selu(fc1) output, 4 MB
__device__ __align__(16) float2 g_o[N_PTS];            // final embedding [n,2]
__device__ float  g_bn_s [128 * H_DIM];                // per-gemm-block partials
__device__ float  g_bn_s2[128 * H_DIM];
__device__ __align__(16) float g_w2a[H_DIM];           // fc2 row 0 * bn scale
__device__ __align__(16) float g_w2b[H_DIM];           // fc2 row 1 * bn scale
__device__ float  g_b2[2];                             // folded bias
__device__ float  g_part[512];                         // denom partials (full-matrix)

// ---------------- helpers ----------------------------------------------------
__device__ __forceinline__ float selu_f(float x) {
    const float alpha = 1.6732632423543772f;
    const float scale = 1.0507009873554805f;
    return x > 0.0f ? scale * x : scale * alpha * expm1f(x);
}

// FFMA-pipe reciprocal: bit-hack seed + 2 Newton steps -> ~1e-6 rel.
__device__ __forceinline__ float fast_rcp(float x) {
    float y = __int_as_float(0x7EF311C3 - __float_as_int(x));
    y = y * fmaf(-x, y, 2.0f);
    y = y * fmaf(-x, y, 2.0f);
    return y;
}

__device__ __forceinline__ float rcp1p(float2 a, float2 p) {
    float dx = a.x - p.x, dy = a.y - p.y;
    return fast_rcp(fmaf(dx, dx, fmaf(dy, dy, 1.0f)));
}

__device__ __forceinline__ u32 bfpack(__nv_bfloat16 a, __nv_bfloat16 b) {
    return (u32)__bfloat16_as_ushort(a) |
           ((u32)__bfloat16_as_ushort(b) << 16);
}

__device__ __forceinline__ void split2(float x, float y, u32& h, u32& l) {
    __nv_bfloat16 hx = __float2bfloat16_rn(x), hy = __float2bfloat16_rn(y);
    float rx = x - __bfloat162float(hx);
    float ry = y - __bfloat162float(hy);
    h = bfpack(hx, hy);
    l = bfpack(__float2bfloat16_rn(rx), __float2bfloat16_rn(ry));
}

__device__ __forceinline__ void mma_bf16(float c[4], const u32 a[4],
                                         u32 b0, u32 b1) {
    asm volatile(
        "mma.sync.aligned.m16n8k16.row.col.f32.bf16.bf16.f32 "
        "{%0,%1,%2,%3}, {%4,%5,%6,%7}, {%8,%9}, {%0,%1,%2,%3};\n"
        : "+f"(c[0]), "+f"(c[1]), "+f"(c[2]), "+f"(c[3])
        : "r"(a[0]), "r"(a[1]), "r"(a[2]), "r"(a[3]), "r"(b0), "r"(b1));
}

// ---------------- K1: o1 = selu(x @ fc_w.T + fc_b), bf16x3 TC + BN partials --
// Block tile 64x128, 8 warps (2m x 4n), BK=16 (49 iters), register prefetch.
__global__ __launch_bounds__(256) void k_gemm1(const float* __restrict__ x,
                                               const float* __restrict__ w,
                                               const float* __restrict__ b) {
    __shared__ u32 As_hi[64 * 12], As_lo[64 * 12];
    __shared__ u32 Bs_hi[128 * 12], Bs_lo[128 * 12];

    const int tid  = threadIdx.x;
    const int row0 = blockIdx.x * 64;
    const int lane = tid & 31;
    const int warp = tid >> 5;
    const int wm = warp >> 2;
    const int wn = warp & 3;
    const int gr = lane >> 2, gc = lane & 3;

    float acc[2][4][4] = {};

    const int a_row = tid >> 2, a_c = tid & 3;   // A: 64 rows x 4 float4
    const int b_n = tid >> 1, b_c = tid & 1;     // B: 128 rows x 2 float4-pairs

    // prefetch first tile into registers
    float4 va  = *(const float4*)&x[(size_t)(row0 + a_row) * F_IN + a_c * 4];
    const float* wp0 = &w[(size_t)b_n * F_IN + b_c * 8];
    float4 vb0 = *(const float4*)wp0;
    float4 vb1 = *(const float4*)(wp0 + 4);

    for (int k0 = 0; k0 < F_IN; k0 += 16) {
        // ---- stage current tile from registers ----
        {
            u32 h0, l0, h1, l1;
            split2(va.x, va.y, h0, l0);
            split2(va.z, va.w, h1, l1);
            *(uint2*)&As_hi[a_row * 12 + a_c * 2] = make_uint2(h0, h1);
            *(uint2*)&As_lo[a_row * 12 + a_c * 2] = make_uint2(l0, l1);
        }
        {
            u32 h0, l0, h1, l1, h2, l2, h3, l3;
            split2(vb0.x, vb0.y, h0, l0); split2(vb0.z, vb0.w, h1, l1);
            split2(vb1.x, vb1.y, h2, l2); split2(vb1.z, vb1.w, h3, l3);
            *(uint4*)&Bs_hi[b_n * 12 + b_c * 4] = make_uint4(h0, h1, h2, h3);
            *(uint4*)&Bs_lo[b_n * 12 + b_c * 4] = make_uint4(l0, l1, l2, l3);
        }
        __syncthreads();

        // ---- prefetch next tile (overlaps MMA below) ----
        if (k0 + 16 < F_IN) {
            va  = *(const float4*)&x[(size_t)(row0 + a_row) * F_IN + (k0 + 16) + a_c * 4];
            const float* wp = &w[(size_t)b_n * F_IN + (k0 + 16) + b_c * 8];
            vb0 = *(const float4*)wp;
            vb1 = *(const float4*)(wp + 4);
        }

        // ---- fragments + mma ----
        u32 ah[2][4], al[2][4];
        #pragma unroll
        for (int mt = 0; mt < 2; mt++) {
            int r = wm * 32 + mt * 16 + gr;
            ah[mt][0] = As_hi[r * 12 + gc];
            ah[mt][1] = As_hi[(r + 8) * 12 + gc];
            ah[mt][2] = As_hi[r * 12 + gc + 4];
            ah[mt][3] = As_hi[(r + 8) * 12 + gc + 4];
            al[mt][0] = As_lo[r * 12 + gc];
            al[mt][1] = As_lo[(r + 8) * 12 + gc];
            al[mt][2] = As_lo[r * 12 + gc + 4];
            al[mt][3] = As_lo[(r + 8) * 12 + gc + 4];
        }
        #pragma unroll
        for (int nt = 0; nt < 4; nt++) {
            int n = wn * 32 + nt * 8 + gr;
            u32 bh0 = Bs_hi[n * 12 + gc], bh1 = Bs_hi[n * 12 + gc + 4];
            u32 bl0 = Bs_lo[n * 12 + gc], bl1 = Bs_lo[n * 12 + gc + 4];
            #pragma unroll
            for (int mt = 0; mt < 2; mt++) {
                mma_bf16(acc[mt][nt], ah[mt], bh0, bh1);   // hi*hi
                mma_bf16(acc[mt][nt], ah[mt], bl0, bl1);   // hi*lo
                mma_bf16(acc[mt][nt], al[mt], bh0, bh1);   // lo*hi
            }
        }
        __syncthreads();
    }

    // ---- epilogue: bias + selu + store ----
    #pragma unroll
    for (int mt = 0; mt < 2; mt++) {
        int r = row0 + wm * 32 + mt * 16 + gr;
        #pragma unroll
        for (int nt = 0; nt < 4; nt++) {
            int n0 = wn * 32 + nt * 8 + 2 * gc;
            float2 bias = *(const float2*)&b[n0];
            float2 o0, o1;
            o0.x = selu_f(acc[mt][nt][0] + bias.x);
            o0.y = selu_f(acc[mt][nt][1] + bias.y);
            o1.x = selu_f(acc[mt][nt][2] + bias.x);
            o1.y = selu_f(acc[mt][nt][3] + bias.y);
            *(float2*)&g_o1[(size_t)r * H_DIM + n0]       = o0;
            *(float2*)&g_o1[(size_t)(r + 8) * H_DIM + n0] = o1;
        }
    }

    // ---- fused BN partial sums over this block's 64 rows (L2-hot) ----
    __syncthreads();     // block-scope fence: epilogue stores visible below
    if (tid < H_DIM) {
        float s = 0.f, s2 = 0.f;
        for (int r = 0; r < 64; r++) {
            float v = g_o1[(size_t)(row0 + r) * H_DIM + tid];
            s += v;
            s2 = fmaf(v, v, s2);
        }
        g_bn_s [blockIdx.x * H_DIM + tid] = s;
        g_bn_s2[blockIdx.x * H_DIM + tid] = s2;
    }
}

// ---------------- K2: finalize BN, fold into fc2 weights ---------------------
__global__ void k_bn_finalize(const float* __restrict__ gamma,
                              const float* __restrict__ beta,
                              const float* __restrict__ w2,
                              const float* __restrict__ b2) {
    int h = threadIdx.x;          // 128
    float s = 0.f, s2 = 0.f;
    for (int blk = 0; blk < 128; blk++) {
        s  += g_bn_s [blk * H_DIM + h];
        s2 += g_bn_s2[blk * H_DIM + h];
    }
    float mu  = s  * (1.0f / N_PTS);
    float var = s2 * (1.0f / N_PTS) - mu * mu;
    float a  = gamma[h] * rsqrtf(var + 1e-5f);
    float bb = beta[h] - mu * a;
    float w0 = w2[h], w1 = w2[H_DIM + h];
    g_w2a[h] = w0 * a;
    g_w2b[h] = w1 * a;
    __shared__ float red0[128], red1[128];
    red0[h] = bb * w0;
    red1[h] = bb * w1;
    __syncthreads();
    for (int off = 64; off > 0; off >>= 1) {
        if (h < off) { red0[h] += red0[h + off]; red1[h] += red1[h + off]; }
        __syncthreads();
    }
    if (h == 0) {
        g_b2[0] = b2[0] + red0[0];
        g_b2[1] = b2[1] + red1[0];
    }
}

// ---------------- K3: o = selu(o1_bn @ fc2'.T + b2'), float4 loads -----------
__global__ __launch_bounds__(256) void k_fc2(float* __restrict__ out_o) {
    int w = threadIdx.x >> 5, lane = threadIdx.x & 31;
    float4 wa = *(const float4*)&g_w2a[lane * 4];
    float4 wb = *(const float4*)&g_w2b[lane * 4];
    #pragma unroll
    for (int rr = 0; rr < 2; rr++) {
        int row = blockIdx.x * 16 + w * 2 + rr;
        float4 v = *(const float4*)&g_o1[(size_t)row * H_DIM + lane * 4];
        float p0 = fmaf(v.x, wa.x, fmaf(v.y, wa.y, fmaf(v.z, wa.z, v.w * wa.w)));
        float p1 = fmaf(v.x, wb.x, fmaf(v.y, wb.y, fmaf(v.z, wb.z, v.w * wb.w)));
        #pragma unroll
        for (int off = 16; off > 0; off >>= 1) {
            p0 += __shfl_xor_sync(0xffffffffu, p0, off);
            p1 += __shfl_xor_sync(0xffffffffu, p1, off);
        }
        if (lane == 0) {
            float2 o;
            o.x = selu_f(p0 + g_b2[0]);
            o.y = selu_f(p1 + g_b2[1]);
            g_o[row] = o;
            *(float2*)&out_o[row * 2] = o;
        }
    }
}

// ---------------- K4: denom partials, FULL matrix (no masking) ---------------
// denom = sum_{all i,j} 1/(1+dis) - N  (diagonal terms are exactly 1).
// grid (32 jblocks, 16 iblocks) = 512 uniform blocks; thread owns 2 i-rows;
// 4 independent accumulator chains (2i x 2j ILP); 256-pt SMEM j-tile.
__global__ __launch_bounds__(256) void k_denom(void) {
    __shared__ float2 oj[256];
    __shared__ float red[256];
    int tid   = threadIdx.x;
    int jbase = blockIdx.x * 256;
    int i0    = blockIdx.y * 512 + tid;

    oj[tid] = g_o[jbase + tid];
    float2 a = g_o[i0];
    float2 c = g_o[i0 + 256];
    __syncthreads();

    float acc0 = 0.f, acc1 = 0.f, acc2 = 0.f, acc3 = 0.f;
    #pragma unroll 4
    for (int j = 0; j < 256; j += 2) {
        float2 p0 = oj[j], p1 = oj[j + 1];
        acc0 += rcp1p(a, p0);
        acc1 += rcp1p(a, p1);
        acc2 += rcp1p(c, p0);
        acc3 += rcp1p(c, p1);
    }
    red[tid] = (acc0 + acc1) + (acc2 + acc3);
    __syncthreads();
    #pragma unroll
    for (int off = 128; off > 0; off >>= 1) {
        if (tid < off) red[tid] += red[tid + off];
        __syncthreads();
    }
    if (tid == 0) g_part[blockIdx.y * 32 + blockIdx.x] = red[0];
}

// ---------------- K5: qij = (1/(1+dis)) * inv_denom (denom folded in) --------
__global__ __launch_bounds__(256) void k_qij(float* __restrict__ out) {
    __shared__ float red[256];
    int tid = threadIdx.x;
    red[tid] = g_part[tid] + g_part[tid + 256];   // identical fixed-order reduce
    __syncthreads();                              // in every block
    #pragma unroll
    for (int off = 128; off > 0; off >>= 1) {
        if (tid < off) red[tid] += red[tid + off];
        __syncthreads();
    }
    float inv = 1.0f / (red[0] - (float)N_PTS);   // subtract diagonal

    int w = tid >> 5, lane = tid & 31;
    int i = blockIdx.y * 8 + w;
    int jbase = blockIdx.x * 1024;
    float2 oi = g_o[i];
    const float4* op4 = (const float4*)g_o;
    float* outrow = out + (size_t)i * N_PTS;
    #pragma unroll
    for (int iter = 0; iter < 8; iter++) {
        int j = jbase + iter * 128 + lane * 4;
        float4 q0 = op4[(j >> 1)];
        float4 q1 = op4[(j >> 1) + 1];
        float4 r;
        { float dx = oi.x - q0.x, dy = oi.y - q0.y;
          r.x = fast_rcp(fmaf(dx, dx, fmaf(dy, dy, 1.0f))) * inv; }
        { float dx = oi.x - q0.z, dy = oi.y - q0.w;
          r.y = fast_rcp(fmaf(dx, dx, fmaf(dy, dy, 1.0f))) * inv; }
        { float dx = oi.x - q1.x, dy = oi.y - q1.y;
          r.z = fast_rcp(fmaf(dx, dx, fmaf(dy, dy, 1.0f))) * inv; }
        { float dx = oi.x - q1.z, dy = oi.y - q1.w;
          r.w = fast_rcp(fmaf(dx, dx, fmaf(dy, dy, 1.0f))) * inv; }
        *(float4*)&outrow[j] = r;
    }
}

// ---------------- launcher ---------------------------------------------------
extern "C" void kernel_launch(void* const* d_in, const int* in_sizes, int n_in,
                              void* d_out, int out_size) {
    (void)in_sizes; (void)n_in; (void)out_size;
    const float* x        = (const float*)d_in[0];
    const float* fc_w     = (const float*)d_in[1];
    const float* fc_b     = (const float*)d_in[2];
    const float* bn_gamma = (const float*)d_in[3];
    const float* bn_beta  = (const float*)d_in[4];
    const float* fc2_w    = (const float*)d_in[5];
    const float* fc2_b    = (const float*)d_in[6];
    float* out = (float*)d_out;
    float* out_qij = out;                               // [n, n]
    float* out_o   = out + (size_t)N_PTS * N_PTS;       // [n, 2]

    k_gemm1<<<N_PTS / 64, 256>>>(x, fc_w, fc_b);
    k_bn_finalize<<<1, 128>>>(bn_gamma, bn_beta, fc2_w, fc2_b);
    k_fc2<<<N_PTS / 16, 256>>>(out_o);
    k_denom<<<dim3(32, 16), 256>>>();
    k_qij<<<dim3(8, 1024), 256>>>(out_qij);
}